// round 16
// baseline (speedup 1.0000x reference)
#include <cuda_runtime.h>
#include <math.h>

#define BB 4
#define LL 2048
#define DD 512
#define CH 64
#define NCH (LL/CH)          // 32 chunks per batch
#define NROW (BB*LL)

typedef unsigned long long u64;

// ---- packed fp32x2 helpers ----
__device__ __forceinline__ u64 pk2(float x, float y) {
    u64 r; asm("mov.b64 %0, {%1, %2};" : "=l"(r) : "f"(x), "f"(y)); return r;
}
__device__ __forceinline__ void upk2(u64 v, float& x, float& y) {
    asm("mov.b64 {%0, %1}, %2;" : "=f"(x), "=f"(y) : "l"(v));
}
__device__ __forceinline__ u64 ffma2(u64 a, u64 b, u64 c) {
    u64 d; asm("fma.rn.f32x2 %0, %1, %2, %3;" : "=l"(d) : "l"(a), "l"(b), "l"(c)); return d;
}
__device__ __forceinline__ u64 fadd2(u64 a, u64 b) {
    u64 d; asm("add.rn.f32x2 %0, %1, %2;" : "=l"(d) : "l"(a), "l"(b)); return d;
}
__device__ __forceinline__ u64 fmul2(u64 a, u64 b) {
    u64 d; asm("mul.rn.f32x2 %0, %1, %2;" : "=l"(d) : "l"(a), "l"(b)); return d;
}

// ---- fast tanh ----
__device__ __forceinline__ float fast_tanh(float x) {
    float ax = fabsf(x);
    float e  = __expf(2.0f * ax);
    float t  = 1.0f - __fdividef(2.0f, e + 1.0f);
    return copysignf(t, x);
}

// ---- scratch ----
__device__ float g_xact[NROW*DD];
__device__ float g_stat[NROW*DD];
__device__ float g_odyn[NROW*DD];
__device__ float g_tinvT[BB*NCH*CH*CH];  // [bc][s][t] = Tinv[t][s]   (2 MB)
__device__ float g_gdT  [BB*NCH*CH*CH];  // [bc][s][t] = lam^{t-s} G[t][s] (t>=s)
__device__ float g_lamp[CH];             // lam^{t+1}
__device__ float g_lamf[CH];             // lam^{63-s}

// ============================================================
// 1) prep: x_act = tanh(x)
// ============================================================
__global__ void prep_kernel(const float* __restrict__ x) {
    int row = blockIdx.x;
    int t = threadIdx.x;
    const float4* xin = reinterpret_cast<const float4*>(x + (size_t)row * DD);
    float4* xo = reinterpret_cast<float4*>(g_xact + (size_t)row * DD);
    float4 v = xin[t];
    float4 a;
    a.x = fast_tanh(v.x); a.y = fast_tanh(v.y);
    a.z = fast_tanh(v.z); a.w = fast_tanh(v.w);
    xo[t] = a;
}

// ============================================================
// 1b) chunkmeta: per batch-chunk, compute G = K K^T (64x64),
//     TinvT = transpose of (I + M)^{-1},  M[s,r]=beta*lam^{s-r}G[s][r] (r<s),
//     GdT[s][t] = lam^{t-s} G[t][s] for t>=s else 0.
//     grid = BB*NCH blocks, 256 threads.
// ============================================================
__global__ __launch_bounds__(256) void chunkmeta_kernel(const float* __restrict__ eta_p,
                                                        const float* __restrict__ laml_p) {
    __shared__ float SH[64*65 + 64*65];   // Ks (then reused as Xs) | Gs
    float* Ks = SH;                        // [t][dd] stride 65
    float* Gs = SH + 64*65;                // [t][j]  stride 65
    float* Xs = SH;                        // alias of Ks (after G done)

    int tid = threadIdx.x;
    int bc  = blockIdx.x;
    int b   = bc / NCH;
    int ch  = bc % NCH;
    float beta = eta_p[0];
    float lam  = 1.0f / (1.0f + expf(-laml_p[0]));

    const float* K = g_xact + ((size_t)b * LL + (size_t)ch * CH) * DD;

    int r   = tid & 63;          // G row
    int cgi = tid >> 6;          // 0..3 -> G col group of 16
    float Gacc[16];
    #pragma unroll
    for (int j = 0; j < 16; j++) Gacc[j] = 0.f;

    int lt  = tid >> 2;          // load row 0..63
    int ld0 = (tid & 3) * 16;    // load col base

    for (int dt = 0; dt < 8; dt++) {
        #pragma unroll
        for (int i = 0; i < 4; i++) {
            float4 kv = *reinterpret_cast<const float4*>(K + (size_t)lt * DD + dt * 64 + ld0 + 4 * i);
            Ks[lt * 65 + ld0 + 4*i + 0] = kv.x;
            Ks[lt * 65 + ld0 + 4*i + 1] = kv.y;
            Ks[lt * 65 + ld0 + 4*i + 2] = kv.z;
            Ks[lt * 65 + ld0 + 4*i + 3] = kv.w;
        }
        __syncthreads();
        for (int dd = 0; dd < 64; dd++) {
            float a = Ks[r * 65 + dd];
            #pragma unroll
            for (int j = 0; j < 16; j++)
                Gacc[j] = fmaf(a, Ks[(cgi * 16 + j) * 65 + dd], Gacc[j]);
        }
        __syncthreads();
    }
    #pragma unroll
    for (int j = 0; j < 16; j++) Gs[r * 65 + cgi * 16 + j] = Gacc[j];
    __syncthreads();

    // forward substitution: thread j (<64) computes column j of Tinv
    if (tid < 64) {
        int j = tid;
        Xs[j * 65 + j] = 1.0f;
        for (int s = j + 1; s < 64; s++) {
            float acc = 0.f;
            float f = lam;
            for (int rr = s - 1; rr >= j; rr--) {
                acc = fmaf(f * Gs[s * 65 + rr], Xs[rr * 65 + j], acc);
                f *= lam;
            }
            Xs[s * 65 + j] = -beta * acc;
        }
        // write TinvT row j: TinvT[j][t] = Tinv[t][j]
        float* outT = g_tinvT + (size_t)bc * CH * CH + (size_t)j * CH;
        for (int t = 0; t < 64; t++)
            outT[t] = (t < j) ? 0.f : ((t == j) ? 1.0f : Xs[t * 65 + j]);
        // write GdT row j: GdT[j][t] = lam^{t-j} G[t][j] for t>=j
        float* outG = g_gdT + (size_t)bc * CH * CH + (size_t)j * CH;
        float f = 1.0f;
        for (int t = 0; t < 64; t++) {
            if (t < j) outG[t] = 0.f;
            else { outG[t] = f * Gs[t * 65 + j]; f *= lam; }
        }
        if (bc == 0) {
            float fp = lam;
            for (int i = 0; i < j; i++) fp *= lam;
            g_lamp[j] = fp;                 // lam^{j+1}
            float ff = 1.0f;
            for (int i = 0; i < 63 - j; i++) ff *= lam;
            g_lamf[j] = ff;                 // lam^{63-j}
        }
    }
}

// ============================================================
// 2) SGEMM (unchanged)
// ============================================================
#define BM 128
#define BN 128
#define BK 8

__global__ __launch_bounds__(256) void gemm_kernel(const float* __restrict__ W) {
    __shared__ __align__(16) u64   As2[BK][BM];
    __shared__ __align__(16) float Bs[BK][BN];
    int tid = threadIdx.x;
    int bn = blockIdx.x;
    int bm = blockIdx.y;

    int lr = tid >> 1;
    int lc = (tid & 1) * 4;
    const float* Ag = g_xact + ((size_t)bm * BM + lr) * DD + lc;
    const float* Bg = W      + ((size_t)bn * BN + lr) * DD + lc;

    int tx = tid & 15, ty = tid >> 4;
    int r0 = ty * 8, c0 = tx * 8;

    u64 acc2[8][4];
    #pragma unroll
    for (int i = 0; i < 8; i++)
        #pragma unroll
        for (int j = 0; j < 4; j++) acc2[i][j] = 0ull;

    for (int k0 = 0; k0 < DD; k0 += BK) {
        float4 av = *reinterpret_cast<const float4*>(Ag + k0);
        float4 bv = *reinterpret_cast<const float4*>(Bg + k0);
        As2[lc + 0][lr] = pk2(av.x, av.x);
        As2[lc + 1][lr] = pk2(av.y, av.y);
        As2[lc + 2][lr] = pk2(av.z, av.z);
        As2[lc + 3][lr] = pk2(av.w, av.w);
        Bs[lc + 0][lr] = bv.x; Bs[lc + 1][lr] = bv.y;
        Bs[lc + 2][lr] = bv.z; Bs[lc + 3][lr] = bv.w;
        __syncthreads();
        #pragma unroll
        for (int k = 0; k < BK; k++) {
            ulonglong2 aa0 = *reinterpret_cast<const ulonglong2*>(&As2[k][r0]);
            ulonglong2 aa1 = *reinterpret_cast<const ulonglong2*>(&As2[k][r0 + 2]);
            ulonglong2 aa2 = *reinterpret_cast<const ulonglong2*>(&As2[k][r0 + 4]);
            ulonglong2 aa3 = *reinterpret_cast<const ulonglong2*>(&As2[k][r0 + 6]);
            ulonglong2 bv0 = *reinterpret_cast<const ulonglong2*>(&Bs[k][c0]);
            ulonglong2 bv1 = *reinterpret_cast<const ulonglong2*>(&Bs[k][c0 + 4]);
            u64 ap[8] = {aa0.x, aa0.y, aa1.x, aa1.y, aa2.x, aa2.y, aa3.x, aa3.y};
            u64 bp[4] = {bv0.x, bv0.y, bv1.x, bv1.y};
            #pragma unroll
            for (int i = 0; i < 8; i++)
                #pragma unroll
                for (int j = 0; j < 4; j++)
                    acc2[i][j] = ffma2(ap[i], bp[j], acc2[i][j]);
        }
        __syncthreads();
    }

    #pragma unroll
    for (int i = 0; i < 8; i++) {
        float* cp = g_stat + ((size_t)bm * BM + r0 + i) * DD + bn * BN + c0;
        ulonglong2 w0, w1;
        w0.x = acc2[i][0]; w0.y = acc2[i][1];
        w1.x = acc2[i][2]; w1.y = acc2[i][3];
        *reinterpret_cast<ulonglong2*>(cp)     = w0;
        *reinterpret_cast<ulonglong2*>(cp + 4) = w1;
    }
}

// ============================================================
// 3) CHUNKED scan: warp owns 2 columns (S_A, S_B d-packed, 16 d/lane).
//    Per chunk: P = K@S (64 indep. matvec rows, butterfly reduce),
//    w = TinvT-solve, o = lam^{t+1}P + GdT@w, S = lam64*S + K^T(lamf*w).
//    128 blocks x 256 thr; no serial per-step spine.
// ============================================================
__global__ __launch_bounds__(256) void scan_kernel(const float* __restrict__ eta_p,
                                                   const float* __restrict__ laml_p) {
    __shared__ float s_tinvT[CH*CH];
    __shared__ float s_gdT[CH*CH];
    __shared__ u64   s_stage[8][CH];
    __shared__ u64   s_wstage[8][CH];
    __shared__ float s_lamp[CH];
    __shared__ float s_lamf[CH];

    int tid  = threadIdx.x;
    int wid  = tid >> 5;
    int lane = tid & 31;
    int b    = blockIdx.x >> 5;
    int cg   = blockIdx.x & 31;
    int colA = cg * 16 + wid * 2;

    float beta = eta_p[0];
    float lam  = 1.0f / (1.0f + expf(-laml_p[0]));
    float lam64 = lam;
    #pragma unroll
    for (int i = 0; i < 6; i++) lam64 *= lam64;
    u64 lam64p = pk2(lam64, lam64);

    if (tid < CH) { s_lamp[tid] = g_lamp[tid]; s_lamf[tid] = g_lamf[tid]; }

    const float* Kb  = g_xact + (size_t)b * LL * DD + 4 * lane;
    const float* vbp = g_stat + (size_t)b * LL * DD + colA;
    float*       obp = g_odyn + (size_t)b * LL * DD + colA;

    u64 SA[8], SB[8];
    #pragma unroll
    for (int i = 0; i < 8; i++) { SA[i] = 0ull; SB[i] = 0ull; }

    int t0 = 2 * lane, t1 = t0 + 1;

    for (int ch = 0; ch < NCH; ch++) {
        __syncthreads();   // protect SMEM reuse across chunks
        {
            size_t base = (size_t)(b * NCH + ch) * CH * CH;
            const float4* s1 = reinterpret_cast<const float4*>(g_tinvT + base) + tid * 4;
            const float4* s2 = reinterpret_cast<const float4*>(g_gdT   + base) + tid * 4;
            float4* d1 = reinterpret_cast<float4*>(s_tinvT) + tid * 4;
            float4* d2 = reinterpret_cast<float4*>(s_gdT)   + tid * 4;
            #pragma unroll
            for (int i = 0; i < 4; i++) { d1[i] = s1[i]; d2[i] = s2[i]; }
        }
        __syncthreads();

        const float* Kch = Kb + (size_t)(ch * CH) * DD;

        // ---- P phase ----
        u64 pOwn0 = 0ull, pOwn1 = 0ull;
        ulonglong2 ka0 = *reinterpret_cast<const ulonglong2*>(Kch + 0);
        ulonglong2 ka1 = *reinterpret_cast<const ulonglong2*>(Kch + 128);
        ulonglong2 ka2 = *reinterpret_cast<const ulonglong2*>(Kch + 256);
        ulonglong2 ka3 = *reinterpret_cast<const ulonglong2*>(Kch + 384);
        #pragma unroll 4
        for (int t = 0; t < CH; t++) {
            int tn = (t < CH - 1) ? t + 1 : t;
            const float* kn = Kch + (size_t)tn * DD;
            ulonglong2 kb0 = *reinterpret_cast<const ulonglong2*>(kn + 0);
            ulonglong2 kb1 = *reinterpret_cast<const ulonglong2*>(kn + 128);
            ulonglong2 kb2 = *reinterpret_cast<const ulonglong2*>(kn + 256);
            ulonglong2 kb3 = *reinterpret_cast<const ulonglong2*>(kn + 384);

            u64 aA = 0ull, aB = 0ull;
            aA = ffma2(ka0.x, SA[0], aA); aB = ffma2(ka0.x, SB[0], aB);
            aA = ffma2(ka0.y, SA[1], aA); aB = ffma2(ka0.y, SB[1], aB);
            aA = ffma2(ka1.x, SA[2], aA); aB = ffma2(ka1.x, SB[2], aB);
            aA = ffma2(ka1.y, SA[3], aA); aB = ffma2(ka1.y, SB[3], aB);
            aA = ffma2(ka2.x, SA[4], aA); aB = ffma2(ka2.x, SB[4], aB);
            aA = ffma2(ka2.y, SA[5], aA); aB = ffma2(ka2.y, SB[5], aB);
            aA = ffma2(ka3.x, SA[6], aA); aB = ffma2(ka3.x, SB[6], aB);
            aA = ffma2(ka3.y, SA[7], aA); aB = ffma2(ka3.y, SB[7], aB);
            float ax, ay, bx, by;
            upk2(aA, ax, ay); upk2(aB, bx, by);
            u64 pAB = pk2(ax + ay, bx + by);
            #pragma unroll
            for (int o = 1; o < 32; o <<= 1)
                pAB = fadd2(pAB, __shfl_xor_sync(0xffffffffu, pAB, o));
            if ((t >> 1) == lane) { if (t & 1) pOwn1 = pAB; else pOwn0 = pAB; }
            ka0 = kb0; ka1 = kb1; ka2 = kb2; ka3 = kb3;
        }

        // ---- rhs ----
        {
            float2 v0 = *reinterpret_cast<const float2*>(vbp + (size_t)(ch * CH + t0) * DD);
            float2 v1 = *reinterpret_cast<const float2*>(vbp + (size_t)(ch * CH + t1) * DD);
            float p0x, p0y, p1x, p1y;
            upk2(pOwn0, p0x, p0y); upk2(pOwn1, p1x, p1y);
            float lp0 = s_lamp[t0], lp1 = s_lamp[t1];
            s_stage[wid][t0] = pk2(beta * (v0.x - lp0 * p0x), beta * (v0.y - lp0 * p0y));
            s_stage[wid][t1] = pk2(beta * (v1.x - lp1 * p1x), beta * (v1.y - lp1 * p1y));
        }
        __syncwarp();

        // ---- solve: w = Tinv @ rhs ----
        u64 w0 = 0ull, w1 = 0ull;
        #pragma unroll 8
        for (int s = 0; s < CH; s++) {
            u64 rs = s_stage[wid][s];
            float2 tv = *reinterpret_cast<const float2*>(s_tinvT + s * CH + t0);
            w0 = ffma2(pk2(tv.x, tv.x), rs, w0);
            w1 = ffma2(pk2(tv.y, tv.y), rs, w1);
        }
        s_wstage[wid][t0] = w0;
        s_wstage[wid][t1] = w1;
        __syncwarp();

        // ---- o = lam^{t+1} P + GdT^T w ----
        {
            u64 o0 = 0ull, o1 = 0ull;
            #pragma unroll 8
            for (int s = 0; s < CH; s++) {
                u64 ws = s_wstage[wid][s];
                float2 gd = *reinterpret_cast<const float2*>(s_gdT + s * CH + t0);
                o0 = ffma2(pk2(gd.x, gd.x), ws, o0);
                o1 = ffma2(pk2(gd.y, gd.y), ws, o1);
            }
            float lp0 = s_lamp[t0], lp1 = s_lamp[t1];
            o0 = ffma2(pk2(lp0, lp0), pOwn0, o0);
            o1 = ffma2(pk2(lp1, lp1), pOwn1, o1);
            float2 r0, r1;
            upk2(o0, r0.x, r0.y); upk2(o1, r1.x, r1.y);
            *reinterpret_cast<float2*>(obp + (size_t)(ch * CH + t0) * DD) = r0;
            *reinterpret_cast<float2*>(obp + (size_t)(ch * CH + t1) * DD) = r1;
        }

        // ---- state update: S = lam64*S + sum_s lamf[s] k_s w_s ----
        if (ch < NCH - 1) {
            #pragma unroll
            for (int i = 0; i < 8; i++) {
                SA[i] = fmul2(SA[i], lam64p);
                SB[i] = fmul2(SB[i], lam64p);
            }
            ulonglong2 ua0 = *reinterpret_cast<const ulonglong2*>(Kch + 0);
            ulonglong2 ua1 = *reinterpret_cast<const ulonglong2*>(Kch + 128);
            ulonglong2 ua2 = *reinterpret_cast<const ulonglong2*>(Kch + 256);
            ulonglong2 ua3 = *reinterpret_cast<const ulonglong2*>(Kch + 384);
            #pragma unroll 4
            for (int s = 0; s < CH; s++) {
                int sn = (s < CH - 1) ? s + 1 : s;
                const float* kn = Kch + (size_t)sn * DD;
                ulonglong2 ub0 = *reinterpret_cast<const ulonglong2*>(kn + 0);
                ulonglong2 ub1 = *reinterpret_cast<const ulonglong2*>(kn + 128);
                ulonglong2 ub2 = *reinterpret_cast<const ulonglong2*>(kn + 256);
                ulonglong2 ub3 = *reinterpret_cast<const ulonglong2*>(kn + 384);

                u64 ws = s_wstage[wid][s];
                float wa, wb;
                upk2(ws, wa, wb);
                float lf = s_lamf[s];
                float sa = lf * wa, sb = lf * wb;
                u64 wA2 = pk2(sa, sa), wB2 = pk2(sb, sb);
                SA[0] = ffma2(ua0.x, wA2, SA[0]); SB[0] = ffma2(ua0.x, wB2, SB[0]);
                SA[1] = ffma2(ua0.y, wA2, SA[1]); SB[1] = ffma2(ua0.y, wB2, SB[1]);
                SA[2] = ffma2(ua1.x, wA2, SA[2]); SB[2] = ffma2(ua1.x, wB2, SB[2]);
                SA[3] = ffma2(ua1.y, wA2, SA[3]); SB[3] = ffma2(ua1.y, wB2, SB[3]);
                SA[4] = ffma2(ua2.x, wA2, SA[4]); SB[4] = ffma2(ua2.x, wB2, SB[4]);
                SA[5] = ffma2(ua2.y, wA2, SA[5]); SB[5] = ffma2(ua2.y, wB2, SB[5]);
                SA[6] = ffma2(ua3.x, wA2, SA[6]); SB[6] = ffma2(ua3.x, wB2, SB[6]);
                SA[7] = ffma2(ua3.y, wA2, SA[7]); SB[7] = ffma2(ua3.y, wB2, SB[7]);
                ua0 = ub0; ua1 = ub1; ua2 = ub2; ua3 = ub3;
            }
        }
    }
}

// ============================================================
// 4) LayerNorm
// ============================================================
__global__ void ln_kernel(const float* __restrict__ gamma,
                          const float* __restrict__ lbeta,
                          float* __restrict__ out) {
    int row = blockIdx.x;
    int t = threadIdx.x;
    const float4* sp = reinterpret_cast<const float4*>(g_stat + (size_t)row * DD);
    const float4* op = reinterpret_cast<const float4*>(g_odyn + (size_t)row * DD);
    float4 sv = sp[t], ov = op[t];
    float4 y;
    y.x = sv.x + ov.x; y.y = sv.y + ov.y; y.z = sv.z + ov.z; y.w = sv.w + ov.w;

    float sum = y.x + y.y + y.z + y.w;
    float sq  = y.x*y.x + y.y*y.y + y.z*y.z + y.w*y.w;

    __shared__ float r1[4], r2[4];
    #pragma unroll
    for (int o = 16; o > 0; o >>= 1) {
        sum += __shfl_xor_sync(0xffffffffu, sum, o);
        sq  += __shfl_xor_sync(0xffffffffu, sq, o);
    }
    if ((t & 31) == 0) { r1[t >> 5] = sum; r2[t >> 5] = sq; }
    __syncthreads();
    __shared__ float smu, srs;
    if (t == 0) {
        float ts = r1[0] + r1[1] + r1[2] + r1[3];
        float tq = r2[0] + r2[1] + r2[2] + r2[3];
        float mu = ts * (1.0f / DD);
        float var = tq * (1.0f / DD) - mu * mu;
        smu = mu;
        srs = rsqrtf(var + 1e-5f);
    }
    __syncthreads();
    float mu = smu, rs = srs;

    const float4* gp = reinterpret_cast<const float4*>(gamma);
    const float4* bp = reinterpret_cast<const float4*>(lbeta);
    float4 gv = gp[t], bv = bp[t];
    float4 r;
    r.x = (y.x - mu) * rs * gv.x + bv.x;
    r.y = (y.y - mu) * rs * gv.y + bv.y;
    r.z = (y.z - mu) * rs * gv.z + bv.z;
    r.w = (y.w - mu) * rs * gv.w + bv.w;
    reinterpret_cast<float4*>(out + (size_t)row * DD)[t] = r;
}

// ============================================================
extern "C" void kernel_launch(void* const* d_in, const int* in_sizes, int n_in,
                              void* d_out, int out_size) {
    const float* x     = (const float*)d_in[0];
    const float* W     = (const float*)d_in[1];
    const float* eta   = (const float*)d_in[2];
    const float* laml  = (const float*)d_in[3];
    const float* gamma = (const float*)d_in[4];
    const float* lbeta = (const float*)d_in[5];
    float* out = (float*)d_out;

    // scan at launch index 3 (the one ncu profiles)
    prep_kernel<<<NROW, 128>>>(x);
    chunkmeta_kernel<<<BB * NCH, 256>>>(eta, laml);
    gemm_kernel<<<dim3(DD / BN, NROW / BM), 256>>>(W);
    scan_kernel<<<128, 256>>>(eta, laml);
    ln_kernel<<<NROW, 128>>>(gamma, lbeta, out);
}

// round 17
// speedup vs baseline: 1.3639x; 1.3639x over previous
#include <cuda_runtime.h>
#include <math.h>

#define BB 4
#define LL 2048
#define DD 512
#define CH 64
#define NCH (LL/CH)          // 32 chunks per batch
#define NROW (BB*LL)

typedef unsigned long long u64;

// ---- packed fp32x2 helpers ----
__device__ __forceinline__ u64 pk2(float x, float y) {
    u64 r; asm("mov.b64 %0, {%1, %2};" : "=l"(r) : "f"(x), "f"(y)); return r;
}
__device__ __forceinline__ void upk2(u64 v, float& x, float& y) {
    asm("mov.b64 {%0, %1}, %2;" : "=f"(x), "=f"(y) : "l"(v));
}
__device__ __forceinline__ u64 ffma2(u64 a, u64 b, u64 c) {
    u64 d; asm("fma.rn.f32x2 %0, %1, %2, %3;" : "=l"(d) : "l"(a), "l"(b), "l"(c)); return d;
}
__device__ __forceinline__ u64 fadd2(u64 a, u64 b) {
    u64 d; asm("add.rn.f32x2 %0, %1, %2;" : "=l"(d) : "l"(a), "l"(b)); return d;
}
__device__ __forceinline__ u64 fmul2(u64 a, u64 b) {
    u64 d; asm("mul.rn.f32x2 %0, %1, %2;" : "=l"(d) : "l"(a), "l"(b)); return d;
}

// ---- fast tanh ----
__device__ __forceinline__ float fast_tanh(float x) {
    float ax = fabsf(x);
    float e  = __expf(2.0f * ax);
    float t  = 1.0f - __fdividef(2.0f, e + 1.0f);
    return copysignf(t, x);
}

// ---- scratch ----
__device__ float g_xact[NROW*DD];
__device__ float g_stat[NROW*DD];
__device__ float g_odyn[NROW*DD];
__device__ float g_tinvT[BB*NCH*CH*CH];  // [bc][s][t] = Tinv[t][s]
__device__ float g_gdT  [BB*NCH*CH*CH];  // [bc][s][t] = lam^{t-s} G[t][s] (t>=s)
__device__ float g_lamp[CH];             // lam^{t+1}
__device__ float g_lamf[CH];             // lam^{63-s}

// ============================================================
// 1) prep: x_act = tanh(x)
// ============================================================
__global__ void prep_kernel(const float* __restrict__ x) {
    int row = blockIdx.x;
    int t = threadIdx.x;
    const float4* xin = reinterpret_cast<const float4*>(x + (size_t)row * DD);
    float4* xo = reinterpret_cast<float4*>(g_xact + (size_t)row * DD);
    float4 v = xin[t];
    float4 a;
    a.x = fast_tanh(v.x); a.y = fast_tanh(v.y);
    a.z = fast_tanh(v.z); a.w = fast_tanh(v.w);
    xo[t] = a;
}

// ============================================================
// 1b) chunkmeta (unchanged from R16 — verified correct)
// ============================================================
__global__ __launch_bounds__(256) void chunkmeta_kernel(const float* __restrict__ eta_p,
                                                        const float* __restrict__ laml_p) {
    __shared__ float SH[64*65 + 64*65];
    float* Ks = SH;
    float* Gs = SH + 64*65;
    float* Xs = SH;

    int tid = threadIdx.x;
    int bc  = blockIdx.x;
    int b   = bc / NCH;
    int ch  = bc % NCH;
    float beta = eta_p[0];
    float lam  = 1.0f / (1.0f + expf(-laml_p[0]));

    const float* K = g_xact + ((size_t)b * LL + (size_t)ch * CH) * DD;

    int r   = tid & 63;
    int cgi = tid >> 6;
    float Gacc[16];
    #pragma unroll
    for (int j = 0; j < 16; j++) Gacc[j] = 0.f;

    int lt  = tid >> 2;
    int ld0 = (tid & 3) * 16;

    for (int dt = 0; dt < 8; dt++) {
        #pragma unroll
        for (int i = 0; i < 4; i++) {
            float4 kv = *reinterpret_cast<const float4*>(K + (size_t)lt * DD + dt * 64 + ld0 + 4 * i);
            Ks[lt * 65 + ld0 + 4*i + 0] = kv.x;
            Ks[lt * 65 + ld0 + 4*i + 1] = kv.y;
            Ks[lt * 65 + ld0 + 4*i + 2] = kv.z;
            Ks[lt * 65 + ld0 + 4*i + 3] = kv.w;
        }
        __syncthreads();
        for (int dd = 0; dd < 64; dd++) {
            float a = Ks[r * 65 + dd];
            #pragma unroll
            for (int j = 0; j < 16; j++)
                Gacc[j] = fmaf(a, Ks[(cgi * 16 + j) * 65 + dd], Gacc[j]);
        }
        __syncthreads();
    }
    #pragma unroll
    for (int j = 0; j < 16; j++) Gs[r * 65 + cgi * 16 + j] = Gacc[j];
    __syncthreads();

    if (tid < 64) {
        int j = tid;
        Xs[j * 65 + j] = 1.0f;
        for (int s = j + 1; s < 64; s++) {
            float acc = 0.f;
            float f = lam;
            for (int rr = s - 1; rr >= j; rr--) {
                acc = fmaf(f * Gs[s * 65 + rr], Xs[rr * 65 + j], acc);
                f *= lam;
            }
            Xs[s * 65 + j] = -beta * acc;
        }
        float* outT = g_tinvT + (size_t)bc * CH * CH + (size_t)j * CH;
        for (int t = 0; t < 64; t++)
            outT[t] = (t < j) ? 0.f : ((t == j) ? 1.0f : Xs[t * 65 + j]);
        float* outG = g_gdT + (size_t)bc * CH * CH + (size_t)j * CH;
        float f = 1.0f;
        for (int t = 0; t < 64; t++) {
            if (t < j) outG[t] = 0.f;
            else { outG[t] = f * Gs[t * 65 + j]; f *= lam; }
        }
        if (bc == 0) {
            float fp = lam;
            for (int i = 0; i < j; i++) fp *= lam;
            g_lamp[j] = fp;
            float ff = 1.0f;
            for (int i = 0; i < 63 - j; i++) ff *= lam;
            g_lamf[j] = ff;
        }
    }
}

// ============================================================
// 2) SGEMM (unchanged)
// ============================================================
#define BM 128
#define BN 128
#define BK 8

__global__ __launch_bounds__(256) void gemm_kernel(const float* __restrict__ W) {
    __shared__ __align__(16) u64   As2[BK][BM];
    __shared__ __align__(16) float Bs[BK][BN];
    int tid = threadIdx.x;
    int bn = blockIdx.x;
    int bm = blockIdx.y;

    int lr = tid >> 1;
    int lc = (tid & 1) * 4;
    const float* Ag = g_xact + ((size_t)bm * BM + lr) * DD + lc;
    const float* Bg = W      + ((size_t)bn * BN + lr) * DD + lc;

    int tx = tid & 15, ty = tid >> 4;
    int r0 = ty * 8, c0 = tx * 8;

    u64 acc2[8][4];
    #pragma unroll
    for (int i = 0; i < 8; i++)
        #pragma unroll
        for (int j = 0; j < 4; j++) acc2[i][j] = 0ull;

    for (int k0 = 0; k0 < DD; k0 += BK) {
        float4 av = *reinterpret_cast<const float4*>(Ag + k0);
        float4 bv = *reinterpret_cast<const float4*>(Bg + k0);
        As2[lc + 0][lr] = pk2(av.x, av.x);
        As2[lc + 1][lr] = pk2(av.y, av.y);
        As2[lc + 2][lr] = pk2(av.z, av.z);
        As2[lc + 3][lr] = pk2(av.w, av.w);
        Bs[lc + 0][lr] = bv.x; Bs[lc + 1][lr] = bv.y;
        Bs[lc + 2][lr] = bv.z; Bs[lc + 3][lr] = bv.w;
        __syncthreads();
        #pragma unroll
        for (int k = 0; k < BK; k++) {
            ulonglong2 aa0 = *reinterpret_cast<const ulonglong2*>(&As2[k][r0]);
            ulonglong2 aa1 = *reinterpret_cast<const ulonglong2*>(&As2[k][r0 + 2]);
            ulonglong2 aa2 = *reinterpret_cast<const ulonglong2*>(&As2[k][r0 + 4]);
            ulonglong2 aa3 = *reinterpret_cast<const ulonglong2*>(&As2[k][r0 + 6]);
            ulonglong2 bv0 = *reinterpret_cast<const ulonglong2*>(&Bs[k][c0]);
            ulonglong2 bv1 = *reinterpret_cast<const ulonglong2*>(&Bs[k][c0 + 4]);
            u64 ap[8] = {aa0.x, aa0.y, aa1.x, aa1.y, aa2.x, aa2.y, aa3.x, aa3.y};
            u64 bp[4] = {bv0.x, bv0.y, bv1.x, bv1.y};
            #pragma unroll
            for (int i = 0; i < 8; i++)
                #pragma unroll
                for (int j = 0; j < 4; j++)
                    acc2[i][j] = ffma2(ap[i], bp[j], acc2[i][j]);
        }
        __syncthreads();
    }

    #pragma unroll
    for (int i = 0; i < 8; i++) {
        float* cp = g_stat + ((size_t)bm * BM + r0 + i) * DD + bn * BN + c0;
        ulonglong2 w0, w1;
        w0.x = acc2[i][0]; w0.y = acc2[i][1];
        w1.x = acc2[i][2]; w1.y = acc2[i][3];
        *reinterpret_cast<ulonglong2*>(cp)     = w0;
        *reinterpret_cast<ulonglong2*>(cp + 4) = w1;
    }
}

// ============================================================
// 3) CHUNKED scan, rescheduled: group-of-4 double-buffered K
//    loads in P and update phases; 4 interleaved butterflies.
//    Math identical to R16 (verified, rel_err 4e-7).
// ============================================================
__global__ __launch_bounds__(256) void scan_kernel(const float* __restrict__ eta_p,
                                                   const float* __restrict__ laml_p) {
    __shared__ float s_tinvT[CH*CH];
    __shared__ float s_gdT[CH*CH];
    __shared__ u64   s_stage[8][CH];
    __shared__ u64   s_wstage[8][CH];
    __shared__ float s_lamp[CH];
    __shared__ float s_lamf[CH];

    int tid  = threadIdx.x;
    int wid  = tid >> 5;
    int lane = tid & 31;
    int b    = blockIdx.x >> 5;
    int cg   = blockIdx.x & 31;
    int colA = cg * 16 + wid * 2;

    float beta = eta_p[0];
    float lam  = 1.0f / (1.0f + expf(-laml_p[0]));
    float lam64 = lam;
    #pragma unroll
    for (int i = 0; i < 6; i++) lam64 *= lam64;
    u64 lam64p = pk2(lam64, lam64);

    if (tid < CH) { s_lamp[tid] = g_lamp[tid]; s_lamf[tid] = g_lamf[tid]; }

    const float* Kb  = g_xact + (size_t)b * LL * DD + 4 * lane;
    const float* vbp = g_stat + (size_t)b * LL * DD + colA;
    float*       obp = g_odyn + (size_t)b * LL * DD + colA;

    u64 SA[8], SB[8];
    #pragma unroll
    for (int i = 0; i < 8; i++) { SA[i] = 0ull; SB[i] = 0ull; }

    int t0 = 2 * lane, t1 = t0 + 1;

    ulonglong2 KG0[4][4], KG1[4][4];

#define LOADG(BUF, KCH, TG) do {                                               \
        const float* kp_ = (KCH) + (size_t)(TG) * DD;                          \
        _Pragma("unroll")                                                      \
        for (int i_ = 0; i_ < 4; i_++)                                         \
            _Pragma("unroll")                                                  \
            for (int p_ = 0; p_ < 4; p_++)                                     \
                BUF[i_][p_] = *reinterpret_cast<const ulonglong2*>(            \
                    kp_ + (size_t)i_ * DD + 128 * p_);                         \
    } while (0)

#define PGROUP(BUF, TG) do {                                                   \
        u64 pAB_[4];                                                           \
        _Pragma("unroll")                                                      \
        for (int i_ = 0; i_ < 4; i_++) {                                       \
            u64 aA_ = 0ull, aB_ = 0ull;                                        \
            _Pragma("unroll")                                                  \
            for (int p_ = 0; p_ < 4; p_++) {                                   \
                aA_ = ffma2(BUF[i_][p_].x, SA[2*p_],   aA_);                   \
                aB_ = ffma2(BUF[i_][p_].x, SB[2*p_],   aB_);                   \
                aA_ = ffma2(BUF[i_][p_].y, SA[2*p_+1], aA_);                   \
                aB_ = ffma2(BUF[i_][p_].y, SB[2*p_+1], aB_);                   \
            }                                                                  \
            float ax_, ay_, bx_, by_;                                          \
            upk2(aA_, ax_, ay_); upk2(aB_, bx_, by_);                          \
            pAB_[i_] = pk2(ax_ + ay_, bx_ + by_);                              \
        }                                                                      \
        _Pragma("unroll")                                                      \
        for (int o_ = 1; o_ < 32; o_ <<= 1) {                                  \
            _Pragma("unroll")                                                  \
            for (int i_ = 0; i_ < 4; i_++)                                     \
                pAB_[i_] = fadd2(pAB_[i_],                                     \
                                 __shfl_xor_sync(0xffffffffu, pAB_[i_], o_));  \
        }                                                                      \
        _Pragma("unroll")                                                      \
        for (int i_ = 0; i_ < 4; i_++) {                                       \
            int t_ = (TG) + i_;                                                \
            if ((t_ >> 1) == lane) {                                           \
                if (t_ & 1) pOwn1 = pAB_[i_]; else pOwn0 = pAB_[i_];           \
            }                                                                  \
        }                                                                      \
    } while (0)

#define UGROUP(BUF, SG) do {                                                   \
        _Pragma("unroll")                                                      \
        for (int i_ = 0; i_ < 4; i_++) {                                       \
            u64 ws_ = s_wstage[wid][(SG) + i_];                                \
            float wa_, wb_; upk2(ws_, wa_, wb_);                               \
            float lf_ = s_lamf[(SG) + i_];                                     \
            float sa_ = lf_ * wa_, sb_ = lf_ * wb_;                            \
            u64 wA2_ = pk2(sa_, sa_), wB2_ = pk2(sb_, sb_);                    \
            _Pragma("unroll")                                                  \
            for (int p_ = 0; p_ < 4; p_++) {                                   \
                SA[2*p_]   = ffma2(BUF[i_][p_].x, wA2_, SA[2*p_]);             \
                SB[2*p_]   = ffma2(BUF[i_][p_].x, wB2_, SB[2*p_]);             \
                SA[2*p_+1] = ffma2(BUF[i_][p_].y, wA2_, SA[2*p_+1]);           \
                SB[2*p_+1] = ffma2(BUF[i_][p_].y, wB2_, SB[2*p_+1]);           \
            }                                                                  \
        }                                                                      \
    } while (0)

    for (int ch = 0; ch < NCH; ch++) {
        __syncthreads();
        {
            size_t base = (size_t)(b * NCH + ch) * CH * CH;
            const float4* s1 = reinterpret_cast<const float4*>(g_tinvT + base) + tid * 4;
            const float4* s2 = reinterpret_cast<const float4*>(g_gdT   + base) + tid * 4;
            float4* d1 = reinterpret_cast<float4*>(s_tinvT) + tid * 4;
            float4* d2 = reinterpret_cast<float4*>(s_gdT)   + tid * 4;
            #pragma unroll
            for (int i = 0; i < 4; i++) { d1[i] = s1[i]; d2[i] = s2[i]; }
        }
        __syncthreads();

        const float* Kch = Kb + (size_t)(ch * CH) * DD;

        // ---- P phase: double-buffered groups of 4 ----
        u64 pOwn0 = 0ull, pOwn1 = 0ull;
        LOADG(KG0, Kch, 0);
        #pragma unroll 1
        for (int tg = 0; tg < CH; tg += 8) {
            LOADG(KG1, Kch, tg + 4);
            PGROUP(KG0, tg);
            if (tg + 8 < CH) LOADG(KG0, Kch, tg + 8);
            PGROUP(KG1, tg + 4);
        }

        // ---- rhs ----
        {
            float2 v0 = *reinterpret_cast<const float2*>(vbp + (size_t)(ch * CH + t0) * DD);
            float2 v1 = *reinterpret_cast<const float2*>(vbp + (size_t)(ch * CH + t1) * DD);
            float p0x, p0y, p1x, p1y;
            upk2(pOwn0, p0x, p0y); upk2(pOwn1, p1x, p1y);
            float lp0 = s_lamp[t0], lp1 = s_lamp[t1];
            s_stage[wid][t0] = pk2(beta * (v0.x - lp0 * p0x), beta * (v0.y - lp0 * p0y));
            s_stage[wid][t1] = pk2(beta * (v1.x - lp1 * p1x), beta * (v1.y - lp1 * p1y));
        }
        __syncwarp();

        // ---- solve: w = Tinv @ rhs (split accumulators) ----
        {
            u64 w0a = 0ull, w0b = 0ull, w1a = 0ull, w1b = 0ull;
            #pragma unroll 4
            for (int s = 0; s < CH; s += 2) {
                u64 rs0 = s_stage[wid][s];
                u64 rs1 = s_stage[wid][s + 1];
                float2 tv0 = *reinterpret_cast<const float2*>(s_tinvT + s * CH + t0);
                float2 tv1 = *reinterpret_cast<const float2*>(s_tinvT + (s + 1) * CH + t0);
                w0a = ffma2(pk2(tv0.x, tv0.x), rs0, w0a);
                w1a = ffma2(pk2(tv0.y, tv0.y), rs0, w1a);
                w0b = ffma2(pk2(tv1.x, tv1.x), rs1, w0b);
                w1b = ffma2(pk2(tv1.y, tv1.y), rs1, w1b);
            }
            s_wstage[wid][t0] = fadd2(w0a, w0b);
            s_wstage[wid][t1] = fadd2(w1a, w1b);
        }
        __syncwarp();

        // ---- o = lam^{t+1} P + GdT^T w (split accumulators) ----
        {
            u64 o0a = 0ull, o0b = 0ull, o1a = 0ull, o1b = 0ull;
            #pragma unroll 4
            for (int s = 0; s < CH; s += 2) {
                u64 ws0 = s_wstage[wid][s];
                u64 ws1 = s_wstage[wid][s + 1];
                float2 gd0 = *reinterpret_cast<const float2*>(s_gdT + s * CH + t0);
                float2 gd1 = *reinterpret_cast<const float2*>(s_gdT + (s + 1) * CH + t0);
                o0a = ffma2(pk2(gd0.x, gd0.x), ws0, o0a);
                o1a = ffma2(pk2(gd0.y, gd0.y), ws0, o1a);
                o0b = ffma2(pk2(gd1.x, gd1.x), ws1, o0b);
                o1b = ffma2(pk2(gd1.y, gd1.y), ws1, o1b);
            }
            u64 o0 = fadd2(o0a, o0b), o1 = fadd2(o1a, o1b);
            float lp0 = s_lamp[t0], lp1 = s_lamp[t1];
            o0 = ffma2(pk2(lp0, lp0), pOwn0, o0);
            o1 = ffma2(pk2(lp1, lp1), pOwn1, o1);
            float2 r0, r1;
            upk2(o0, r0.x, r0.y); upk2(o1, r1.x, r1.y);
            *reinterpret_cast<float2*>(obp + (size_t)(ch * CH + t0) * DD) = r0;
            *reinterpret_cast<float2*>(obp + (size_t)(ch * CH + t1) * DD) = r1;
        }

        // ---- state update: S = lam64*S + sum_s lamf[s] k_s w_s ----
        if (ch < NCH - 1) {
            #pragma unroll
            for (int i = 0; i < 8; i++) {
                SA[i] = fmul2(SA[i], lam64p);
                SB[i] = fmul2(SB[i], lam64p);
            }
            LOADG(KG0, Kch, 0);
            #pragma unroll 1
            for (int sg = 0; sg < CH; sg += 8) {
                LOADG(KG1, Kch, sg + 4);
                UGROUP(KG0, sg);
                if (sg + 8 < CH) LOADG(KG0, Kch, sg + 8);
                UGROUP(KG1, sg + 4);
            }
        }
    }
#undef LOADG
#undef PGROUP
#undef UGROUP
}

// ============================================================
// 4) LayerNorm
// ============================================================
__global__ void ln_kernel(const float* __restrict__ gamma,
                          const float* __restrict__ lbeta,
                          float* __restrict__ out) {
    int row = blockIdx.x;
    int t = threadIdx.x;
    const float4* sp = reinterpret_cast<const float4*>(g_stat + (size_t)row * DD);
    const float4* op = reinterpret_cast<const float4*>(g_odyn + (size_t)row * DD);
    float4 sv = sp[t], ov = op[t];
    float4 y;
    y.x = sv.x + ov.x; y.y = sv.y + ov.y; y.z = sv.z + ov.z; y.w = sv.w + ov.w;

    float sum = y.x + y.y + y.z + y.w;
    float sq  = y.x*y.x + y.y*y.y + y.z*y.z + y.w*y.w;

    __shared__ float r1[4], r2[4];
    #pragma unroll
    for (int o = 16; o > 0; o >>= 1) {
        sum += __shfl_xor_sync(0xffffffffu, sum, o);
        sq  += __shfl_xor_sync(0xffffffffu, sq, o);
    }
    if ((t & 31) == 0) { r1[t >> 5] = sum; r2[t >> 5] = sq; }
    __syncthreads();
    __shared__ float smu, srs;
    if (t == 0) {
        float ts = r1[0] + r1[1] + r1[2] + r1[3];
        float tq = r2[0] + r2[1] + r2[2] + r2[3];
        float mu = ts * (1.0f / DD);
        float var = tq * (1.0f / DD) - mu * mu;
        smu = mu;
        srs = rsqrtf(var + 1e-5f);
    }
    __syncthreads();
    float mu = smu, rs = srs;

    const float4* gp = reinterpret_cast<const float4*>(gamma);
    const float4* bp = reinterpret_cast<const float4*>(lbeta);
    float4 gv = gp[t], bv = bp[t];
    float4 r;
    r.x = (y.x - mu) * rs * gv.x + bv.x;
    r.y = (y.y - mu) * rs * gv.y + bv.y;
    r.z = (y.z - mu) * rs * gv.z + bv.z;
    r.w = (y.w - mu) * rs * gv.w + bv.w;
    reinterpret_cast<float4*>(out + (size_t)row * DD)[t] = r;
}

// ============================================================
extern "C" void kernel_launch(void* const* d_in, const int* in_sizes, int n_in,
                              void* d_out, int out_size) {
    const float* x     = (const float*)d_in[0];
    const float* W     = (const float*)d_in[1];
    const float* eta   = (const float*)d_in[2];
    const float* laml  = (const float*)d_in[3];
    const float* gamma = (const float*)d_in[4];
    const float* lbeta = (const float*)d_in[5];
    float* out = (float*)d_out;

    // scan at launch index 3 (the one ncu profiles)
    prep_kernel<<<NROW, 128>>>(x);
    chunkmeta_kernel<<<BB * NCH, 256>>>(eta, laml);
    gemm_kernel<<<dim3(DD / BN, NROW / BM), 256>>>(W);
    scan_kernel<<<128, 256>>>(eta, laml);
    ln_kernel<<<NROW, 128>>>(gamma, lbeta, out);
}